// round 1
// baseline (speedup 1.0000x reference)
#include <cuda_runtime.h>

// ---------------- problem constants (fixed shapes) ----------------
#define B_  4
#define D_  118
#define H_  32
#define W_  88
#define C_  80
#define NX_ 360
#define NY_ 360

#define NPTS   (B_ * D_ * H_ * W_)            // 1,329,152 points
#define SCR_N  ((size_t)B_ * NX_ * NY_ * C_)  // 41,472,000 floats (~166 MB)

// Scratch: channel-last accumulation grid (B, X, Y, C) so a point's 80
// channel atomics are a contiguous 320B run instead of 80 scattered sectors.
__device__ float g_scratch[SCR_N];
__device__ float g_combine[B_ * 9];
__device__ float g_trans[B_ * 3];

// ---------------- kernel 0: per-batch combine = rots @ inv(intrins) --------
__global__ void setup_kernel(const float* __restrict__ rots,
                             const float* __restrict__ trans,
                             const float* __restrict__ intrins) {
    int b = threadIdx.x;
    if (b >= B_) return;
    const float* K = intrins + b * 9;
    // 3x3 inverse via adjugate in double, rounded to fp32 (tracks jnp.linalg.inv)
    double a00 = K[0], a01 = K[1], a02 = K[2];
    double a10 = K[3], a11 = K[4], a12 = K[5];
    double a20 = K[6], a21 = K[7], a22 = K[8];
    double det = a00 * (a11 * a22 - a12 * a21)
               - a01 * (a10 * a22 - a12 * a20)
               + a02 * (a10 * a21 - a11 * a20);
    double id = 1.0 / det;
    float inv[9];
    inv[0] = (float)(( a11 * a22 - a12 * a21) * id);
    inv[1] = (float)((-(a01 * a22 - a02 * a21)) * id);
    inv[2] = (float)(( a01 * a12 - a02 * a11) * id);
    inv[3] = (float)((-(a10 * a22 - a12 * a20)) * id);
    inv[4] = (float)(( a00 * a22 - a02 * a20) * id);
    inv[5] = (float)((-(a00 * a12 - a02 * a10)) * id);
    inv[6] = (float)(( a10 * a21 - a11 * a20) * id);
    inv[7] = (float)((-(a00 * a21 - a01 * a20)) * id);
    inv[8] = (float)(( a00 * a11 - a01 * a10) * id);
    const float* R = rots + b * 9;
    for (int i = 0; i < 3; i++)
        for (int j = 0; j < 3; j++)
            g_combine[b * 9 + i * 3 + j] =
                R[i * 3 + 0] * inv[0 * 3 + j] +
                R[i * 3 + 1] * inv[1 * 3 + j] +
                R[i * 3 + 2] * inv[2 * 3 + j];
    for (int i = 0; i < 3; i++) g_trans[b * 3 + i] = trans[b * 3 + i];
}

// ---------------- kernel 1: zero the scratch grid --------------------------
__global__ void zero_kernel() {
    size_t i = (size_t)blockIdx.x * blockDim.x + threadIdx.x;
    size_t n4 = SCR_N / 4;
    if (i < n4) {
        float4 z = make_float4(0.f, 0.f, 0.f, 0.f);
        reinterpret_cast<float4*>(g_scratch)[i] = z;
    }
}

// ---------------- kernel 2: warp-per-point geometry + scatter-add ----------
__global__ void __launch_bounds__(256)
scatter_kernel(const float* __restrict__ x, const float* __restrict__ frustum) {
    int warp = (int)(((size_t)blockIdx.x * blockDim.x + threadIdx.x) >> 5);
    int lane = threadIdx.x & 31;
    if (warp >= NPTS) return;

    int p = warp;
    // p = ((b*D + d)*H + h)*W + w
    int w  = p % W_;
    int t  = p / W_;
    int h  = t % H_;  t /= H_;
    int d  = t % D_;
    int b  = t / D_;

    const float* fr = frustum + ((size_t)(d * H_ + h) * W_ + w) * 3;
    float fu = fr[0], fv = fr[1], fd = fr[2];      // broadcast loads (uniform in warp)
    float p0 = fu * fd, p1 = fv * fd, p2 = fd;

    const float* cmb = g_combine + b * 9;
    const float* tr  = g_trans   + b * 3;
    float gx = cmb[0] * p0 + cmb[1] * p1 + cmb[2] * p2 + tr[0];
    float gy = cmb[3] * p0 + cmb[4] * p1 + cmb[5] * p2 + tr[1];
    float gz = cmb[6] * p0 + cmb[7] * p1 + cmb[8] * p2 + tr[2];

    // voxelization: matches ((geom - BX_LO)/DX).astype(int32)  (trunc toward 0)
    int cx = (int)((gx - (-54.0f)) / 0.3f);
    int cy = (int)((gy - (-54.0f)) / 0.3f);
    int cz = (int)((gz - (-10.0f)) / 20.0f);

    if ((unsigned)cx < (unsigned)NX_ && (unsigned)cy < (unsigned)NY_ && cz == 0) {
        size_t obase = ((size_t)(b * NX_ + cx) * NY_ + cy) * C_;
        const float* xr = x + (size_t)p * C_;
        #pragma unroll
        for (int j = 0; j < C_; j += 32) {
            int c = j + lane;
            if (c < C_)  // 80 = 32+32+16
                atomicAdd(&g_scratch[obase + c], xr[c]);
        }
    }
}

// ---------------- kernel 3: (B, XY, C) -> (B, C, XY) transpose -------------
__global__ void transpose_kernel(float* __restrict__ out) {
    __shared__ float tile[32][33];
    int b  = blockIdx.z;
    int c0 = blockIdx.y * 32;
    int q0 = blockIdx.x * 32;   // flattened ixy = ix*NY + iy
    int tx = threadIdx.x, ty = threadIdx.y;

    int c = c0 + tx;
    int q = q0 + ty;
    if (c < C_)
        tile[ty][tx] = g_scratch[((size_t)b * (NX_ * NY_) + q) * C_ + c];
    __syncthreads();

    int c2 = c0 + ty;
    int q2 = q0 + tx;
    if (c2 < C_)
        out[((size_t)b * C_ + c2) * (size_t)(NX_ * NY_) + q2] = tile[tx][ty];
}

// ---------------- launch ----------------------------------------------------
extern "C" void kernel_launch(void* const* d_in, const int* in_sizes, int n_in,
                              void* d_out, int out_size) {
    const float* x       = (const float*)d_in[0];
    const float* rots    = (const float*)d_in[1];
    const float* trans   = (const float*)d_in[2];
    const float* intrins = (const float*)d_in[3];
    const float* frustum = (const float*)d_in[4];
    float* out = (float*)d_out;

    setup_kernel<<<1, 32>>>(rots, trans, intrins);

    int zb = (int)((SCR_N / 4 + 255) / 256);
    zero_kernel<<<zb, 256>>>();

    // 8 warps (8 points) per 256-thread block; NPTS divisible by 8
    scatter_kernel<<<NPTS / 8, 256>>>(x, frustum);

    dim3 tb(32, 32);
    dim3 tg((NX_ * NY_) / 32, (C_ + 31) / 32, B_);
    transpose_kernel<<<tg, tb>>>(out);
}

// round 2
// speedup vs baseline: 1.1160x; 1.1160x over previous
#include <cuda_runtime.h>

// ---------------- problem constants (fixed shapes) ----------------
#define B_   4
#define D_   118
#define H_   32
#define W_   88
#define C_   80
#define NX_  360
#define NY_  360
#define XY_  (NX_ * NY_)                      // 129600
#define PPB  (D_ * H_ * W_)                   // 332,288 points per batch

#define SCR_N  ((size_t)B_ * XY_ * C_)        // 41,472,000 floats (~166 MB)

// Channel-last accumulation grid (B, X, Y, C): one point's 80 channel adds
// form a contiguous 320B run. Zero-initialized at module load; the fused
// transpose re-zeros it every launch, so every graph replay sees zeros.
__device__ float g_scratch[SCR_N];
__device__ float g_combine[B_ * 9];
__device__ float g_trans[B_ * 3];

// ---------------- kernel 0: per-batch combine = rots @ inv(intrins) --------
__global__ void setup_kernel(const float* __restrict__ rots,
                             const float* __restrict__ trans,
                             const float* __restrict__ intrins) {
    int b = threadIdx.x;
    if (b >= B_) return;
    const float* K = intrins + b * 9;
    double a00 = K[0], a01 = K[1], a02 = K[2];
    double a10 = K[3], a11 = K[4], a12 = K[5];
    double a20 = K[6], a21 = K[7], a22 = K[8];
    double det = a00 * (a11 * a22 - a12 * a21)
               - a01 * (a10 * a22 - a12 * a20)
               + a02 * (a10 * a21 - a11 * a20);
    double id = 1.0 / det;
    float inv[9];
    inv[0] = (float)(( a11 * a22 - a12 * a21) * id);
    inv[1] = (float)((-(a01 * a22 - a02 * a21)) * id);
    inv[2] = (float)(( a01 * a12 - a02 * a11) * id);
    inv[3] = (float)((-(a10 * a22 - a12 * a20)) * id);
    inv[4] = (float)(( a00 * a22 - a02 * a20) * id);
    inv[5] = (float)((-(a00 * a12 - a02 * a10)) * id);
    inv[6] = (float)(( a10 * a21 - a11 * a20) * id);
    inv[7] = (float)((-(a00 * a21 - a01 * a20)) * id);
    inv[8] = (float)(( a00 * a11 - a01 * a10) * id);
    const float* R = rots + b * 9;
    for (int i = 0; i < 3; i++)
        for (int j = 0; j < 3; j++)
            g_combine[b * 9 + i * 3 + j] =
                R[i * 3 + 0] * inv[0 * 3 + j] +
                R[i * 3 + 1] * inv[1 * 3 + j] +
                R[i * 3 + 2] * inv[2 * 3 + j];
    for (int i = 0; i < 3; i++) g_trans[b * 3 + i] = trans[b * 3 + i];
}

// 16B vector reduction to global (sm_90+): 4 channels per atomic lane-op.
__device__ __forceinline__ void red_add_v4(float* ptr, float4 v) {
    asm volatile("red.global.add.v4.f32 [%0], {%1, %2, %3, %4};"
                 :: "l"(ptr), "f"(v.x), "f"(v.y), "f"(v.z), "f"(v.w)
                 : "memory");
}

// ---------------- kernel 1: warp-per-point geometry + vector scatter -------
// One batch per launch: the 41.5MB scratch slice stays L2-resident for the
// atomics AND for the transpose that follows.
__global__ void __launch_bounds__(256)
scatter_kernel(const float* __restrict__ x, const float* __restrict__ frustum,
               int b) {
    int warp = (int)(((size_t)blockIdx.x * blockDim.x + threadIdx.x) >> 5);
    int lane = threadIdx.x & 31;
    if (warp >= PPB) return;

    // local point index within batch: ((d*H + h)*W + w)
    int p = warp;
    int w = p % W_;
    int t = p / W_;
    int h = t % H_;
    int d = t / H_;

    const float* fr = frustum + ((size_t)(d * H_ + h) * W_ + w) * 3;
    float fu = fr[0], fv = fr[1], fd = fr[2];   // uniform within warp
    float p0 = fu * fd, p1 = fv * fd, p2 = fd;

    const float* cmb = g_combine + b * 9;
    const float* tr  = g_trans   + b * 3;
    float gx = cmb[0] * p0 + cmb[1] * p1 + cmb[2] * p2 + tr[0];
    float gy = cmb[3] * p0 + cmb[4] * p1 + cmb[5] * p2 + tr[1];
    float gz = cmb[6] * p0 + cmb[7] * p1 + cmb[8] * p2 + tr[2];

    // matches ((geom - BX_LO)/DX).astype(int32) — truncation toward zero
    int cx = (int)((gx + 54.0f) / 0.3f);
    int cy = (int)((gy + 54.0f) / 0.3f);
    int cz = (int)((gz + 10.0f) / 20.0f);

    if ((unsigned)cx < (unsigned)NX_ && (unsigned)cy < (unsigned)NY_ && cz == 0) {
        size_t obase = ((size_t)(b * NX_ + cx) * NY_ + cy) * C_;   // 320B aligned
        if (lane < C_ / 4) {  // lanes 0..19: one float4 each
            const float4* xr4 =
                reinterpret_cast<const float4*>(x + ((size_t)b * PPB + p) * C_);
            float4 v = __ldcs(xr4 + lane);     // streaming: don't evict scratch
            red_add_v4(&g_scratch[obase + 4 * lane], v);
        }
    }
}

// ---------------- kernel 2: fused transpose + re-zero ----------------------
// Per batch: (XY, C) -> (C, XY), then zero the scratch tile for next replay.
// Tile: 64 q-rows x 80 channels = contiguous 20KB chunk of scratch.
__global__ void __launch_bounds__(256)
transpose_zero_kernel(float* __restrict__ out, int b) {
    __shared__ float s[64 * 81];   // [q][c], pad 81: stride mod 32 = 17 (coprime)
    int t  = threadIdx.x;
    int q0 = blockIdx.x * 64;

    float4* scr4 = reinterpret_cast<float4*>(g_scratch);
    size_t tile4 = ((size_t)b * XY_ + q0) * (C_ / 4);

    // load 1280 float4 (contiguous), scatter to smem, write zeros back
    const float4 z4 = make_float4(0.f, 0.f, 0.f, 0.f);
    #pragma unroll
    for (int k = 0; k < 5; k++) {
        int idx = t + k * 256;
        float4 v = scr4[tile4 + idx];
        int q  = idx / (C_ / 4);
        int c4 = idx % (C_ / 4);
        s[q * 81 + c4 * 4 + 0] = v.x;
        s[q * 81 + c4 * 4 + 1] = v.y;
        s[q * 81 + c4 * 4 + 2] = v.z;
        s[q * 81 + c4 * 4 + 3] = v.w;
        scr4[tile4 + idx] = z4;               // re-zero for next replay
    }
    __syncthreads();

    // write 5120 scalars: consecutive lanes -> consecutive q (coalesced),
    // smem column reads stride 81 (conflict-free)
    #pragma unroll
    for (int k = 0; k < 20; k++) {
        int o = t + k * 256;
        int c = o / 64;
        int q = o % 64;
        out[((size_t)b * C_ + c) * XY_ + q0 + q] = s[q * 81 + c];
    }
}

// ---------------- launch ----------------------------------------------------
extern "C" void kernel_launch(void* const* d_in, const int* in_sizes, int n_in,
                              void* d_out, int out_size) {
    const float* x       = (const float*)d_in[0];
    const float* rots    = (const float*)d_in[1];
    const float* trans   = (const float*)d_in[2];
    const float* intrins = (const float*)d_in[3];
    const float* frustum = (const float*)d_in[4];
    float* out = (float*)d_out;

    setup_kernel<<<1, 32>>>(rots, trans, intrins);

    // Interleave per batch so the 41.5MB scratch slice is L2-resident across
    // scatter (atomics) and transpose (reads + re-zero).
    for (int b = 0; b < B_; b++) {
        scatter_kernel<<<PPB / 8, 256>>>(x, frustum, b);        // 8 pts/block
        transpose_zero_kernel<<<XY_ / 64, 256>>>(out, b);       // 2025 blocks
    }
}

// round 3
// speedup vs baseline: 1.1203x; 1.0038x over previous
#include <cuda_runtime.h>

// ---------------- problem constants (fixed shapes) ----------------
#define B_   4
#define D_   118
#define H_   32
#define W_   88
#define C_   80
#define NX_  360
#define NY_  360
#define XY_  (NX_ * NY_)                      // 129600
#define PPB  (D_ * H_ * W_)                   // 332,288 points per batch

#define SCR_N  ((size_t)B_ * XY_ * C_)        // 41,472,000 floats (~166 MB)

// Channel-last accumulation grid (B, X, Y, C): one point's 80 channel adds
// form a contiguous 320B run. Zero-initialized at module load; the fused
// transpose re-zeros it every launch, so every graph replay sees zeros.
__device__ float g_scratch[SCR_N];
__device__ float g_combine[B_ * 9];
__device__ float g_trans[B_ * 3];

// ---------------- kernel 0: per-batch combine = rots @ inv(intrins) --------
__global__ void setup_kernel(const float* __restrict__ rots,
                             const float* __restrict__ trans,
                             const float* __restrict__ intrins) {
    int b = threadIdx.x;
    if (b >= B_) return;
    const float* K = intrins + b * 9;
    double a00 = K[0], a01 = K[1], a02 = K[2];
    double a10 = K[3], a11 = K[4], a12 = K[5];
    double a20 = K[6], a21 = K[7], a22 = K[8];
    double det = a00 * (a11 * a22 - a12 * a21)
               - a01 * (a10 * a22 - a12 * a20)
               + a02 * (a10 * a21 - a11 * a20);
    double id = 1.0 / det;
    float inv[9];
    inv[0] = (float)(( a11 * a22 - a12 * a21) * id);
    inv[1] = (float)((-(a01 * a22 - a02 * a21)) * id);
    inv[2] = (float)(( a01 * a12 - a02 * a11) * id);
    inv[3] = (float)((-(a10 * a22 - a12 * a20)) * id);
    inv[4] = (float)(( a00 * a22 - a02 * a20) * id);
    inv[5] = (float)((-(a00 * a12 - a02 * a10)) * id);
    inv[6] = (float)(( a10 * a21 - a11 * a20) * id);
    inv[7] = (float)((-(a00 * a21 - a01 * a20)) * id);
    inv[8] = (float)(( a00 * a11 - a01 * a10) * id);
    const float* R = rots + b * 9;
    for (int i = 0; i < 3; i++)
        for (int j = 0; j < 3; j++)
            g_combine[b * 9 + i * 3 + j] =
                R[i * 3 + 0] * inv[0 * 3 + j] +
                R[i * 3 + 1] * inv[1 * 3 + j] +
                R[i * 3 + 2] * inv[2 * 3 + j];
    for (int i = 0; i < 3; i++) g_trans[b * 3 + i] = trans[b * 3 + i];
}

// 16B vector reduction to global (sm_90+): 4 channels per atomic lane-op.
__device__ __forceinline__ void red_add_v4(float* ptr, float4 v) {
    asm volatile("red.global.add.v4.f32 [%0], {%1, %2, %3, %4};"
                 :: "l"(ptr), "f"(v.x), "f"(v.y), "f"(v.z), "f"(v.w)
                 : "memory");
}

// ---------------- kernel 1: warp-per-point geometry + vector scatter -------
// One batch per launch: the 41.5MB scratch slice stays L2-resident for the
// atomics AND for the transpose that follows.
__global__ void __launch_bounds__(256)
scatter_kernel(const float* __restrict__ x, const float* __restrict__ frustum,
               int b) {
    int warp = (int)(((size_t)blockIdx.x * blockDim.x + threadIdx.x) >> 5);
    int lane = threadIdx.x & 31;
    if (warp >= PPB) return;

    // local point index within batch: ((d*H + h)*W + w)
    int p = warp;
    int w = p % W_;
    int t = p / W_;
    int h = t % H_;
    int d = t / H_;

    const float* fr = frustum + ((size_t)(d * H_ + h) * W_ + w) * 3;
    float fu = fr[0], fv = fr[1], fd = fr[2];   // uniform within warp
    float p0 = fu * fd, p1 = fv * fd, p2 = fd;

    const float* cmb = g_combine + b * 9;
    const float* tr  = g_trans   + b * 3;
    float gx = cmb[0] * p0 + cmb[1] * p1 + cmb[2] * p2 + tr[0];
    float gy = cmb[3] * p0 + cmb[4] * p1 + cmb[5] * p2 + tr[1];
    float gz = cmb[6] * p0 + cmb[7] * p1 + cmb[8] * p2 + tr[2];

    // matches ((geom - BX_LO)/DX).astype(int32) — truncation toward zero
    int cx = (int)((gx + 54.0f) / 0.3f);
    int cy = (int)((gy + 54.0f) / 0.3f);
    int cz = (int)((gz + 10.0f) / 20.0f);

    if ((unsigned)cx < (unsigned)NX_ && (unsigned)cy < (unsigned)NY_ && cz == 0) {
        size_t obase = ((size_t)(b * NX_ + cx) * NY_ + cy) * C_;   // 320B aligned
        if (lane < C_ / 4) {  // lanes 0..19: one float4 each
            const float4* xr4 =
                reinterpret_cast<const float4*>(x + ((size_t)b * PPB + p) * C_);
            float4 v = __ldcs(xr4 + lane);     // streaming: don't evict scratch
            red_add_v4(&g_scratch[obase + 4 * lane], v);
        }
    }
}

// ---------------- kernel 2: fused transpose + re-zero ----------------------
// Per batch: (XY, C) -> (C, XY), then zero the scratch tile for next replay.
// Tile: 64 q-rows x 80 channels = contiguous 20KB chunk of scratch.
__global__ void __launch_bounds__(256)
transpose_zero_kernel(float* __restrict__ out, int b) {
    __shared__ float s[64 * 81];   // [q][c], pad 81: stride mod 32 = 17 (coprime)
    int t  = threadIdx.x;
    int q0 = blockIdx.x * 64;

    float4* scr4 = reinterpret_cast<float4*>(g_scratch);
    size_t tile4 = ((size_t)b * XY_ + q0) * (C_ / 4);

    // load 1280 float4 (contiguous), scatter to smem, write zeros back
    const float4 z4 = make_float4(0.f, 0.f, 0.f, 0.f);
    #pragma unroll
    for (int k = 0; k < 5; k++) {
        int idx = t + k * 256;
        float4 v = scr4[tile4 + idx];
        int q  = idx / (C_ / 4);
        int c4 = idx % (C_ / 4);
        s[q * 81 + c4 * 4 + 0] = v.x;
        s[q * 81 + c4 * 4 + 1] = v.y;
        s[q * 81 + c4 * 4 + 2] = v.z;
        s[q * 81 + c4 * 4 + 3] = v.w;
        scr4[tile4 + idx] = z4;               // re-zero for next replay
    }
    __syncthreads();

    // write 5120 scalars: consecutive lanes -> consecutive q (coalesced),
    // smem column reads stride 81 (conflict-free)
    #pragma unroll
    for (int k = 0; k < 20; k++) {
        int o = t + k * 256;
        int c = o / 64;
        int q = o % 64;
        out[((size_t)b * C_ + c) * XY_ + q0 + q] = s[q * 81 + c];
    }
}

// ---------------- launch ----------------------------------------------------
extern "C" void kernel_launch(void* const* d_in, const int* in_sizes, int n_in,
                              void* d_out, int out_size) {
    const float* x       = (const float*)d_in[0];
    const float* rots    = (const float*)d_in[1];
    const float* trans   = (const float*)d_in[2];
    const float* intrins = (const float*)d_in[3];
    const float* frustum = (const float*)d_in[4];
    float* out = (float*)d_out;

    setup_kernel<<<1, 32>>>(rots, trans, intrins);

    // Interleave per batch so the 41.5MB scratch slice is L2-resident across
    // scatter (atomics) and transpose (reads + re-zero).
    for (int b = 0; b < B_; b++) {
        scatter_kernel<<<PPB / 8, 256>>>(x, frustum, b);        // 8 pts/block
        transpose_zero_kernel<<<XY_ / 64, 256>>>(out, b);       // 2025 blocks
    }
}